// round 2
// baseline (speedup 1.0000x reference)
#include <cuda_runtime.h>

#define HW 16384
#define NPIX (16 * 128 * 128)
#define OFF_PI 0
#define OFF_MU 2097152
#define OFF_SIG 35651584
#define OFF_G 37748736

// shared layout (floats)
#define SH_W 0        // 152*128 = 19456 : Wmu transposed [c][o]
#define SH_S 19456    // 152*8 = 1216    : Wsig transposed [c][j]
#define SH_BMU 20672  // 128
#define SH_WPI 20800  // 128 (8x16)
#define SH_MISC 20928 // 32 : bpi[0..7], bsig[8..15], Wg[16..23], bg[24]
#define SH_DIST 20960 // 128*8
#define SH_RHO 21984  // 128*8
#define SH_FLOATS 23008
#define SMEM_BYTES (SH_FLOATS * 4)

__device__ __forceinline__ unsigned long long pack2(float a, float b) {
    unsigned long long r;
    asm("mov.b64 %0, {%1,%2};" : "=l"(r) : "f"(a), "f"(b));
    return r;
}
__device__ __forceinline__ unsigned long long ffma2(unsigned long long a,
                                                    unsigned long long b,
                                                    unsigned long long c) {
    unsigned long long d;
    asm("fma.rn.f32x2 %0, %1, %2, %3;" : "=l"(d) : "l"(a), "l"(b), "l"(c));
    return d;
}
__device__ __forceinline__ float2 unpack2(unsigned long long v) {
    float2 f;
    asm("mov.b64 {%0,%1}, %2;" : "=f"(f.x), "=f"(f.y) : "l"(v));
    return f;
}

extern "C" __global__ void __launch_bounds__(128)
gmm_block_kernel(const float* __restrict__ x, const float* __restrict__ pi_in,
                 const float* __restrict__ mu, const float* __restrict__ sigma,
                 const float* __restrict__ Wpi, const float* __restrict__ bpi,
                 const float* __restrict__ Wmu, const float* __restrict__ bmu,
                 const float* __restrict__ Wsig, const float* __restrict__ bsig,
                 const float* __restrict__ Wg, const float* __restrict__ bg,
                 float* __restrict__ out) {
    extern __shared__ float sh[];
    float* shW = sh + SH_W;
    float* shS = sh + SH_S;
    float* shBmu = sh + SH_BMU;
    float* shWpi = sh + SH_WPI;
    float* shMisc = sh + SH_MISC;
    float* shDist = sh + SH_DIST;
    float* shRho = sh + SH_RHO;
    const int tid = threadIdx.x;

    // --- cooperative weight staging ---
    {
        // thread tid owns Wmu row o = tid; STS addresses c*128+tid are
        // conflict-free across the warp; per-thread LDGs walk one row (L1 reuse)
        const float* wrow = Wmu + tid * 152;
#pragma unroll 4
        for (int c = 0; c < 152; c++) shW[c * 128 + tid] = wrow[c];
    }
    for (int i = tid; i < 1216; i += 128) {
        int c = i >> 3, j = i & 7;
        shS[c * 8 + j] = Wsig[j * 152 + c];
    }
    shBmu[tid] = bmu[tid];
    shWpi[tid] = Wpi[tid];
    if (tid < 8) {
        shMisc[tid] = bpi[tid];
        shMisc[8 + tid] = bsig[tid];
        shMisc[16 + tid] = Wg[tid];
    }
    if (tid == 0) shMisc[24] = bg[0];
    __syncthreads();

    const int p = blockIdx.x * 128 + tid;
    const int b = p >> 14;
    const int hw = p & (HW - 1);
    const float* xp = x + (b * 16) * HW + hw;
    const float* mup = mu + (b * 128) * HW + hw;
    const float* pip = pi_in + (b * 8) * HW + hw;
    const float* sgp = sigma + (b * 8) * HW + hw;

    float xv[16];
#pragma unroll
    for (int c = 0; c < 16; c++) xv[c] = xp[c * HW];

    // packed accumulators: acc[j] holds mu_new outputs (2j, 2j+1)
    unsigned long long acc[64];
#pragma unroll
    for (int j = 0; j < 64; j++) acc[j] = pack2(shBmu[2 * j], shBmu[2 * j + 1]);

#define MM_STEP(VAL, WPTR)                                                   \
    do {                                                                     \
        unsigned long long vv_ = pack2((VAL), (VAL));                        \
        const ulonglong2* w2_ = reinterpret_cast<const ulonglong2*>(WPTR);   \
        _Pragma("unroll") for (int q_ = 0; q_ < 32; q_++) {                  \
            ulonglong2 w_ = w2_[q_];                                         \
            acc[2 * q_] = ffma2(w_.x, vv_, acc[2 * q_]);                     \
            acc[2 * q_ + 1] = ffma2(w_.y, vv_, acc[2 * q_ + 1]);             \
        }                                                                    \
    } while (0)

    // channels 0..15 : x  (reload from L1 to keep this loop rolled/small)
#pragma unroll 2
    for (int c = 0; c < 16; c++) {
        float v = xp[c * HW];
        MM_STEP(v, shW + c * 128);
    }

    // channels 16..143 : mu — fused with dist (dens) computation, single pass
    for (int k = 0; k < 8; k++) {
        float dk = 0.f;
        const float* mrow = mup + (k * 16) * HW;
        const float* wbase = shW + (16 + k * 16) * 128;
#pragma unroll 4
        for (int c = 0; c < 16; c++) {
            float v = mrow[c * HW];
            float d = xp[c * HW] - v;
            dk = fmaf(d, d, dk);
            MM_STEP(v, wbase + c * 128);
        }
        shDist[tid + k * 128] = dk;
    }

    // dens / alpha / rho
    float alpha[8], piv[8];
#pragma unroll
    for (int k = 0; k < 8; k++) piv[k] = pip[k * HW];
#pragma unroll
    for (int k = 0; k < 8; k++) {
        float sg = sgp[k * HW];
        float s2 = sg * sg;
        float t = 6.283185307179586f * s2;
        float t2 = t * t, t4 = t2 * t2;
        float pref = 1.0f / (t4 * t4);               // (2*pi*s2)^-8
        float dk = shDist[tid + k * 128];
        float dens = pref * __expf(-dk / (2.0f * s2));
        float a = piv[k] * dens;
        alpha[k] = a;
        shRho[tid + k * 128] = a * dens;
    }

    // pi_new = softmax(Wpi @ [pi, alpha] + bpi)
    float pin[8];
    {
        float z[8];
        float zmax = -1e30f;
#pragma unroll
        for (int j = 0; j < 8; j++) {
            float zj = shMisc[j];
#pragma unroll
            for (int i = 0; i < 8; i++) {
                zj = fmaf(shWpi[j * 16 + i], piv[i], zj);
                zj = fmaf(shWpi[j * 16 + 8 + i], alpha[i], zj);
            }
            z[j] = zj;
            zmax = fmaxf(zmax, zj);
        }
        float s = 0.f;
#pragma unroll
        for (int j = 0; j < 8; j++) {
            z[j] = __expf(z[j] - zmax);
            s += z[j];
        }
        float inv = 1.0f / s;
#pragma unroll
        for (int j = 0; j < 8; j++) {
            pin[j] = z[j] * inv;
            out[OFF_PI + (b * 8 + j) * HW + hw] = pin[j];
        }
    }

    // channels 144..151 : rho
#pragma unroll 2
    for (int c = 0; c < 8; c++) {
        float v = shRho[tid + c * 128];
        MM_STEP(v, shW + (144 + c) * 128);
    }

    // sigma-stage matvec accumulators (8 outputs = 4 packed pairs)
    unsigned long long sac[4];
#pragma unroll
    for (int j = 0; j < 4; j++)
        sac[j] = pack2(shMisc[8 + 2 * j], shMisc[8 + 2 * j + 1]);

#define SIG_STEP(VAL, CH)                                                    \
    do {                                                                     \
        unsigned long long vv_ = pack2((VAL), (VAL));                        \
        const ulonglong2* r_ =                                               \
            reinterpret_cast<const ulonglong2*>(shS + (CH) * 8);             \
        ulonglong2 wa_ = r_[0];                                              \
        ulonglong2 wb_ = r_[1];                                              \
        sac[0] = ffma2(wa_.x, vv_, sac[0]);                                  \
        sac[1] = ffma2(wa_.y, vv_, sac[1]);                                  \
        sac[2] = ffma2(wb_.x, vv_, sac[2]);                                  \
        sac[3] = ffma2(wb_.y, vv_, sac[3]);                                  \
    } while (0)

#pragma unroll
    for (int c = 0; c < 16; c++) SIG_STEP(xv[c], c);

    // relu -> mu_new : store + feed sigma matvec straight from registers
    float* outMu = out + OFF_MU + (b * 128) * HW + hw;
#pragma unroll
    for (int j = 0; j < 64; j++) {
        float2 f = unpack2(acc[j]);
        f.x = fmaxf(f.x, 0.f);
        f.y = fmaxf(f.y, 0.f);
        acc[j] = pack2(f.x, f.y);
        outMu[(2 * j) * HW] = f.x;
        outMu[(2 * j + 1) * HW] = f.y;
        SIG_STEP(f.x, 16 + 2 * j);
        SIG_STEP(f.y, 17 + 2 * j);
    }
#pragma unroll
    for (int c = 0; c < 8; c++) SIG_STEP(shRho[tid + c * 128], 144 + c);

    // sigma_new = exp(relu(.))
    float sn[8];
#pragma unroll
    for (int j = 0; j < 4; j++) {
        float2 f = unpack2(sac[j]);
        sn[2 * j] = __expf(fmaxf(f.x, 0.f));
        sn[2 * j + 1] = __expf(fmaxf(f.y, 0.f));
    }
#pragma unroll
    for (int k = 0; k < 8; k++) out[OFF_SIG + (b * 8 + k) * HW + hw] = sn[k];

    // dens2 + gamma
    float g = shMisc[24];
#pragma unroll
    for (int k = 0; k < 8; k++) {
        float dk = 0.f;
#pragma unroll
        for (int jj = 0; jj < 8; jj++) {
            float2 f = unpack2(acc[k * 8 + jj]);
            float d0 = xv[2 * jj] - f.x;
            float d1 = xv[2 * jj + 1] - f.y;
            dk = fmaf(d0, d0, dk);
            dk = fmaf(d1, d1, dk);
        }
        float s2 = sn[k] * sn[k];
        float t = 6.283185307179586f * s2;
        float t2 = t * t, t4 = t2 * t2;
        float pref = 1.0f / (t4 * t4);
        float dens2 = pref * __expf(-dk / (2.0f * s2));
        g = fmaf(shMisc[16 + k], pin[k] * dens2, g);
    }
    out[OFF_G + p] = 1.0f / (1.0f + __expf(-g));
}

extern "C" void kernel_launch(void* const* d_in, const int* in_sizes, int n_in,
                              void* d_out, int out_size) {
    (void)in_sizes;
    (void)n_in;
    (void)out_size;
    const float* x = (const float*)d_in[0];
    const float* pi = (const float*)d_in[1];
    const float* mu = (const float*)d_in[2];
    const float* sigma = (const float*)d_in[3];
    const float* Wpi = (const float*)d_in[4];
    const float* bpi = (const float*)d_in[5];
    const float* Wmu = (const float*)d_in[6];
    const float* bmu = (const float*)d_in[7];
    const float* Wsig = (const float*)d_in[8];
    const float* bsig = (const float*)d_in[9];
    const float* Wg = (const float*)d_in[10];
    const float* bg = (const float*)d_in[11];
    float* out = (float*)d_out;

    cudaFuncSetAttribute(gmm_block_kernel,
                         cudaFuncAttributeMaxDynamicSharedMemorySize,
                         SMEM_BYTES);
    dim3 grid(NPIX / 128);
    dim3 block(128);
    gmm_block_kernel<<<grid, block, SMEM_BYTES>>>(
        x, pi, mu, sigma, Wpi, bpi, Wmu, bmu, Wsig, bsig, Wg, bg, out);
}